// round 7
// baseline (speedup 1.0000x reference)
#include <cuda_runtime.h>
#include <math.h>

#define EPSF 1e-10f
#define NPAD 1024

// ---------------- scratch (device globals; no allocation allowed) ----------------
// padded gathered points, channel-major: X[level][b][ch][n], n padded to 1024 with zeros
__device__ float g_X[7864320];   // sum_l 8*c_l*1024 = 524288+1048576+2097152+4194304
__device__ float g_Y[7864320];
__device__ float g_normX[4 * 8 * 1024];
__device__ float g_normY[4 * 8 * 1024];
__device__ float g_meanX[4 * 8 * 512];
__device__ float g_meanY[4 * 8 * 512];
__device__ unsigned g_rowmin[4 * 8 * 1024];
__device__ unsigned g_colmin[4 * 8 * 1024];
__device__ float g_covabs[32];   // [l*8+b]  sum |covX-covY|
__device__ float g_sm[32];       // [l*8+b]  style + mean-diff term

// ---------------- init ----------------
__global__ void init_kernel() {
    int t = blockIdx.x * 256 + threadIdx.x;
    if (t < 4 * 8 * 1024) {
        g_rowmin[t] = 0x7F7FFFFFu;   // FLT_MAX bits; distances are >0 so uint order == float order
        g_colmin[t] = 0x7F7FFFFFu;
    }
    if (t < 32) g_covabs[t] = 0.f;
}

// ---------------- gather: feat (B,c,h,w) + idx -> Xt[c][1024] zero-padded ----------------
__global__ void gather_kernel(const float* __restrict__ tgt, const float* __restrict__ gen,
                              const int* __restrict__ idx, int c, int hw, int N, int off) {
    int b = blockIdx.y, tsel = blockIdx.z;
    const float* src = tsel ? gen : tgt;
    float* dst = (tsel ? g_Y : g_X) + off;
    int t = blockIdx.x * 256 + threadIdx.x;     // grid.x = c*4 so t < c*1024 always
    int ch = t >> 10, n = t & 1023;
    float v = 0.f;
    if (n < N) {
        int pos = idx ? idx[b * N + n] : n;
        v = src[((size_t)b * c + ch) * hw + pos];
    }
    dst[((size_t)b * c + ch) * NPAD + n] = v;   // coalesced over n
}

// ---------------- per-point L2 norms (column sums, coalesced over n) ----------------
__global__ void norms_kernel(int c, int off, int lvl) {
    int b = blockIdx.y, tsel = blockIdx.z;
    const float* src = (tsel ? g_Y : g_X) + off + (size_t)b * c * NPAD;
    float* dst = (tsel ? g_normY : g_normX) + (lvl * 8 + b) * 1024;
    int n = blockIdx.x * 256 + threadIdx.x;     // grid.x = 4
    float s = 0.f;
    for (int ch = 0; ch < c; ch++) { float v = src[ch * NPAD + n]; s += v * v; }
    dst[n] = sqrtf(s);
}

// ---------------- per-channel means (warp per channel) ----------------
__global__ void means_kernel(int c, int N, int off, int lvl) {
    int b = blockIdx.y, tsel = blockIdx.z;
    const float* src = (tsel ? g_Y : g_X) + off + (size_t)b * c * NPAD;
    float* dst = (tsel ? g_meanY : g_meanX) + (lvl * 8 + b) * 512;
    int ch = blockIdx.x * 8 + (threadIdx.x >> 5);
    int lane = threadIdx.x & 31;
    if (ch >= c) return;
    float s = 0.f;
    for (int n = lane; n < NPAD; n += 32) s += src[ch * NPAD + n];  // pad zeros add 0
#pragma unroll
    for (int o = 16; o; o >>= 1) s += __shfl_xor_sync(0xFFFFFFFFu, s, o);
    if (lane == 0) dst[ch] = s / (float)N;
}

// ---------------- Gram + cosine distance + row/col min (64x64 tile, 4x4/thread) ----------------
__global__ void __launch_bounds__(256) gram_kernel(int c, int N, int off, int lvl) {
    int b = blockIdx.z;
    const float* Xb = g_X + off + (size_t)b * c * NPAD;
    const float* Yb = g_Y + off + (size_t)b * c * NPAD;
    int i0 = blockIdx.y * 64, j0 = blockIdx.x * 64;
    __shared__ float As[16][64], Bs[16][64];
    int tx = threadIdx.x & 15, ty = threadIdx.x >> 4;
    float acc[4][4];
#pragma unroll
    for (int i = 0; i < 4; i++)
#pragma unroll
        for (int j = 0; j < 4; j++) acc[i][j] = 0.f;

    for (int k0 = 0; k0 < c; k0 += 16) {
#pragma unroll
        for (int r = 0; r < 4; r++) {
            int id = r * 256 + threadIdx.x;
            int kk = id >> 6, nn = id & 63;
            As[kk][nn] = Xb[(k0 + kk) * NPAD + i0 + nn];   // contiguous over nn, conflict-free STS
            Bs[kk][nn] = Yb[(k0 + kk) * NPAD + j0 + nn];
        }
        __syncthreads();
#pragma unroll
        for (int k = 0; k < 16; k++) {
            float4 a4 = *reinterpret_cast<const float4*>(&As[k][ty * 4]);
            float4 b4 = *reinterpret_cast<const float4*>(&Bs[k][tx * 4]);
            float a[4] = {a4.x, a4.y, a4.z, a4.w};
            float bb[4] = {b4.x, b4.y, b4.z, b4.w};
#pragma unroll
            for (int i = 0; i < 4; i++)
#pragma unroll
                for (int j = 0; j < 4; j++) acc[i][j] += a[i] * bb[j];
        }
        __syncthreads();
    }

    // epilogue: cosine distance + tile-local min reduction
    __shared__ unsigned srow[64], scol[64];
    if (threadIdx.x < 64) { srow[threadIdx.x] = 0x7F7FFFFFu; scol[threadIdx.x] = 0x7F7FFFFFu; }
    __syncthreads();
    const float* nX = g_normX + (lvl * 8 + b) * 1024;
    const float* nY = g_normY + (lvl * 8 + b) * 1024;
    float nx[4], ny[4];
#pragma unroll
    for (int i = 0; i < 4; i++) {
        nx[i] = nX[i0 + ty * 4 + i] + EPSF;
        ny[i] = nY[j0 + tx * 4 + i] + EPSF;
    }
#pragma unroll
    for (int i = 0; i < 4; i++) {
        int gi = i0 + ty * 4 + i;
#pragma unroll
        for (int j = 0; j < 4; j++) {
            int gj = j0 + tx * 4 + j;
            if (gi < N && gj < N) {
                float d = 1.0f - acc[i][j] / nx[i] / ny[j];   // matches ref's double division
                unsigned u = __float_as_uint(d);              // d > 0 for random gaussian features
                atomicMin(&srow[ty * 4 + i], u);
                atomicMin(&scol[tx * 4 + j], u);
            }
        }
    }
    __syncthreads();
    if (threadIdx.x < 64) {
        int gi = i0 + threadIdx.x, gj = j0 + threadIdx.x;
        if (gi < N) atomicMin(&g_rowmin[(lvl * 8 + b) * 1024 + gi], srow[threadIdx.x]);
        if (gj < N) atomicMin(&g_colmin[(lvl * 8 + b) * 1024 + gj], scol[threadIdx.x]);
    }
}

// ---------------- fused covariance |covX - covY| (upper triangle tiles only) ----------------
__global__ void __launch_bounds__(256) cov_kernel(int c, int N, int off, int lvl) {
    int a0 = blockIdx.y * 64, b0 = blockIdx.x * 64;
    if (a0 > b0) return;                        // symmetry: weight off-diag elements by 2
    int b = blockIdx.z;
    const float* Xb = g_X + off + (size_t)b * c * NPAD;
    const float* Yb = g_Y + off + (size_t)b * c * NPAD;
    __shared__ float Ax[64][17], Bx[64][17], Ay[64][17], By[64][17];
    int tx = threadIdx.x & 15, ty = threadIdx.x >> 4;
    float accx[4][4], accy[4][4];
#pragma unroll
    for (int i = 0; i < 4; i++)
#pragma unroll
        for (int j = 0; j < 4; j++) { accx[i][j] = 0.f; accy[i][j] = 0.f; }

    int la = threadIdx.x >> 2;                  // 0..63  (row within tile)
    int lk = (threadIdx.x & 3) * 4;             // float4 slot within 16-wide K chunk

    for (int k0 = 0; k0 < NPAD; k0 += 16) {
        float4 v;
        v = *reinterpret_cast<const float4*>(&Xb[(a0 + la) * NPAD + k0 + lk]);
        Ax[la][lk + 0] = v.x; Ax[la][lk + 1] = v.y; Ax[la][lk + 2] = v.z; Ax[la][lk + 3] = v.w;
        v = *reinterpret_cast<const float4*>(&Xb[(b0 + la) * NPAD + k0 + lk]);
        Bx[la][lk + 0] = v.x; Bx[la][lk + 1] = v.y; Bx[la][lk + 2] = v.z; Bx[la][lk + 3] = v.w;
        v = *reinterpret_cast<const float4*>(&Yb[(a0 + la) * NPAD + k0 + lk]);
        Ay[la][lk + 0] = v.x; Ay[la][lk + 1] = v.y; Ay[la][lk + 2] = v.z; Ay[la][lk + 3] = v.w;
        v = *reinterpret_cast<const float4*>(&Yb[(b0 + la) * NPAD + k0 + lk]);
        By[la][lk + 0] = v.x; By[la][lk + 1] = v.y; By[la][lk + 2] = v.z; By[la][lk + 3] = v.w;
        __syncthreads();
#pragma unroll
        for (int k = 0; k < 16; k++) {
            float xa[4], xb[4], ya[4], yb[4];
#pragma unroll
            for (int i = 0; i < 4; i++) {
                xa[i] = Ax[ty * 4 + i][k];      // broadcast within half-warp
                ya[i] = Ay[ty * 4 + i][k];
                xb[i] = Bx[tx * 4 + i][k];      // 2-way conflict max (pad 17)
                yb[i] = By[tx * 4 + i][k];
            }
#pragma unroll
            for (int i = 0; i < 4; i++)
#pragma unroll
                for (int j = 0; j < 4; j++) {
                    accx[i][j] += xa[i] * xb[j];
                    accy[i][j] += ya[i] * yb[j];
                }
        }
        __syncthreads();
    }

    const float* mX = g_meanX + (lvl * 8 + b) * 512;
    const float* mY = g_meanY + (lvl * 8 + b) * 512;
    float mxa[4], mxb[4], mya[4], myb[4];
#pragma unroll
    for (int i = 0; i < 4; i++) {
        mxa[i] = mX[a0 + ty * 4 + i]; mxb[i] = mX[b0 + tx * 4 + i];
        mya[i] = mY[a0 + ty * 4 + i]; myb[i] = mY[b0 + tx * 4 + i];
    }
    float inv = 1.0f / (float)(N - 1);
    float fN = (float)N;
    float local = 0.f;
#pragma unroll
    for (int i = 0; i < 4; i++) {
        int ga = a0 + ty * 4 + i;
#pragma unroll
        for (int j = 0; j < 4; j++) {
            int gb = b0 + tx * 4 + j;
            if (ga <= gb) {
                float cx = (accx[i][j] - fN * mxa[i] * mxb[j]) * inv;
                float cy = (accy[i][j] - fN * mya[i] * myb[j]) * inv;
                float w = (ga < gb) ? 2.f : 1.f;
                local += w * fabsf(cx - cy);
            }
        }
    }
#pragma unroll
    for (int o = 16; o; o >>= 1) local += __shfl_xor_sync(0xFFFFFFFFu, local, o);
    __shared__ float red[8];
    if ((threadIdx.x & 31) == 0) red[threadIdx.x >> 5] = local;
    __syncthreads();
    if (threadIdx.x == 0) {
        float s = 0.f;
        for (int i = 0; i < 8; i++) s += red[i];
        atomicAdd(&g_covabs[lvl * 8 + b], s);
    }
}

// ---------------- style (max of mean-mins) + mean-abs-diff term, per (b, level) ----------------
__global__ void stylered_kernel() {
    int b = blockIdx.x, l = blockIdx.y;
    const int cs_[4] = {64, 128, 256, 512};
    const int Ns_[4] = {1000, 1000, 1000, 1024};
    int c = cs_[l], N = Ns_[l];
    int base = (l * 8 + b) * 1024;
    float rs = 0.f, csu = 0.f;
    for (int i = threadIdx.x; i < N; i += 256) {
        rs  += __uint_as_float(g_rowmin[base + i]);
        csu += __uint_as_float(g_colmin[base + i]);
    }
    int mbase = (l * 8 + b) * 512;
    float ms = 0.f;
    for (int ch = threadIdx.x; ch < c; ch += 256)
        ms += fabsf(g_meanX[mbase + ch] - g_meanY[mbase + ch]);

    __shared__ float s1[256], s2[256], s3[256];
    int t = threadIdx.x;
    s1[t] = rs; s2[t] = csu; s3[t] = ms;
    __syncthreads();
    for (int o = 128; o; o >>= 1) {
        if (t < o) { s1[t] += s1[t + o]; s2[t] += s2[t + o]; s3[t] += s3[t + o]; }
        __syncthreads();
    }
    if (t == 0) {
        float style = fmaxf(s1[0] / (float)N, s2[0] / (float)N);
        g_sm[l * 8 + b] = style + s3[0] / (float)c;
    }
}

// ---------------- final scalar ----------------
__global__ void final_kernel(float* __restrict__ out) {
    int t = threadIdx.x;   // 32 threads = 4 levels * 8 batches
    const int cs_[4] = {64, 128, 256, 512};
    int l = t >> 3;
    float cc = (float)cs_[l];
    float v = g_sm[t] + g_covabs[t] / (cc * cc);
#pragma unroll
    for (int o = 16; o; o >>= 1) v += __shfl_xor_sync(0xFFFFFFFFu, v, o);
    if (t == 0) out[0] = v * 0.125f;   // mean over batch
}

// ---------------- host launcher ----------------
extern "C" void kernel_launch(void* const* d_in, const int* in_sizes, int n_in,
                              void* d_out, int out_size) {
    (void)out_size;
    const float* tgt[4] = {nullptr, nullptr, nullptr, nullptr};
    const float* gen[4] = {nullptr, nullptr, nullptr, nullptr};
    const int* idxp[3]  = {nullptr, nullptr, nullptr};
    int ni = 0;
    for (int i = 0; i < n_in; i++) {
        int lvl = -1;
        switch (in_sizes[i]) {
            case 33554432: lvl = 0; break;   // 8*64*256*256
            case 16777216: lvl = 1; break;   // 8*128*128*128
            case 8388608:  lvl = 2; break;   // 8*256*64*64
            case 4194304:  lvl = 3; break;   // 8*512*32*32
            case 8000: if (ni < 3) idxp[ni++] = (const int*)d_in[i]; break;
            default: break;
        }
        if (lvl >= 0) {
            if (!tgt[lvl]) tgt[lvl] = (const float*)d_in[i];
            else           gen[lvl] = (const float*)d_in[i];
        }
    }

    const int cs[4]   = {64, 128, 256, 512};
    const int Ns[4]   = {1000, 1000, 1000, 1024};
    const int hws[4]  = {65536, 16384, 4096, 1024};
    const int offs[4] = {0, 524288, 1572864, 3670016};

    init_kernel<<<256, 256>>>();
    for (int l = 0; l < 4; l++)
        gather_kernel<<<dim3(cs[l] * 4, 8, 2), 256>>>(
            tgt[l], gen[l], (l < 3) ? idxp[l] : nullptr, cs[l], hws[l], Ns[l], offs[l]);
    for (int l = 0; l < 4; l++) {
        norms_kernel<<<dim3(4, 8, 2), 256>>>(cs[l], offs[l], l);
        means_kernel<<<dim3(cs[l] / 8, 8, 2), 256>>>(cs[l], Ns[l], offs[l], l);
    }
    for (int l = 0; l < 4; l++) {
        gram_kernel<<<dim3(16, 16, 8), 256>>>(cs[l], Ns[l], offs[l], l);
        cov_kernel<<<dim3(cs[l] / 64, cs[l] / 64, 8), 256>>>(cs[l], Ns[l], offs[l], l);
    }
    stylered_kernel<<<dim3(8, 4), 256>>>();
    final_kernel<<<1, 32>>>((float*)d_out);
}